// round 9
// baseline (speedup 1.0000x reference)
#include <cuda_runtime.h>
#include <math.h>

#define NN 50000
#define NE 800000
#define DF 64
#define MM 11
#define NDEPTH 3

// ---------------- scratch (device globals — no allocation allowed) ----------
__device__ int   g_cnt[NN];
__device__ int   g_cur[NN];          // running CSR fill cursor (init = rowptr)
__device__ int   g_rowptr[NN + 1];
__device__ float g_dinv[NN];
__device__ int2  g_edge[NE];         // (col, val-bits) per CSR slot
__device__ float g_y1[NN * DF];
__device__ float g_y2[NN * DF];
__device__ float g_C[4][4];          // out[L] = sum_k C[L][k] * S^k x

// ---------------- init: zero cnt + compute coefficients ---------------------
// Jacobi recursion with l=-1, r=1: (l+r)/(r-l)=0, 2/(r-l)=1.
__global__ void init_kernel(const float* __restrict__ alphas,
                            const float* __restrict__ w,
                            const float* __restrict__ a_arr,
                            const float* __restrict__ b_arr) {
    int i = blockIdx.x * blockDim.x + threadIdx.x;
    if (i < NN) g_cnt[i] = 0;

    if (blockIdx.x == 0) {
        __shared__ double sC[MM][4][4];
        int m = threadIdx.x;
        if (m < MM) {
            double a = (double)a_arr[m];
            double b = (double)b_arr[m];
            double wm = (double)w[m];
            double al[NDEPTH];
            for (int d = 0; d < NDEPTH; d++) al[d] = (double)alphas[d * MM + m];

            double Pm2[4] = {1.0, 0.0, 0.0, 0.0};              // P0
            double coef1 = (a - b) * 0.5;
            double coef2 = (a + b + 2.0) * 0.5;
            double Pm1[4] = {al[0] * coef1, al[0] * coef2, 0.0, 0.0};  // P1

            for (int k = 0; k < 4; k++) { sC[m][0][k] = wm * Pm2[k]; sC[m][1][k] = wm * Pm1[k]; }

            for (int Lk = 2; Lk <= NDEPTH; Lk++) {
                double Lf = (double)Lk;
                double coef_l     = 2.0 * Lf * (Lf + a + b) * (2.0 * Lf - 2.0 + a + b);
                double coef_lm1_1 = (2.0 * Lf + a + b - 1.0) * (2.0 * Lf + a + b) * (2.0 * Lf + a + b - 2.0);
                double coef_lm1_2 = (2.0 * Lf + a + b - 1.0) * (a * a - b * b);
                double coef_lm2   = 2.0 * (Lf - 1.0 + a) * (Lf - 1.0 + b) * (2.0 * Lf + a + b);
                double alL   = al[Lk - 1];
                double alLm1 = al[Lk - 2];
                double tmp1 = alL * (coef_lm1_1 / coef_l);
                double tmp2 = alL * (coef_lm1_2 / coef_l);
                double tmp3 = alL * alLm1 * (coef_lm2 / coef_l);
                double PL[4];
                PL[0] = -tmp2 * Pm1[0] - tmp3 * Pm2[0];
                for (int k = 1; k < 4; k++)
                    PL[k] = tmp1 * Pm1[k - 1] - tmp2 * Pm1[k] - tmp3 * Pm2[k];
                for (int k = 0; k < 4; k++) sC[m][Lk][k] = wm * PL[k];
                for (int k = 0; k < 4; k++) { Pm2[k] = Pm1[k]; Pm1[k] = PL[k]; }
            }
        }
        __syncthreads();
        int t = threadIdx.x;
        if (t < 16) {
            int L = t >> 2, k = t & 3;
            double s = 0.0;
            for (int mm = 0; mm < MM; mm++) s += sC[mm][L][k];
            g_C[L][k] = (float)s;
        }
    }
}

// ---------------- degree histogram ------------------------------------------
__global__ void __launch_bounds__(256) hist_kernel(const int* __restrict__ row) {
    int e = blockIdx.x * blockDim.x + threadIdx.x;
    if (e < NE) atomicAdd(&g_cnt[row[e]], 1);
}

// ---------------- scan (+ dinv + cursor init), single block -----------------
__global__ void __launch_bounds__(1024) scan_kernel() {
    const int T = 1024;
    __shared__ int ssum[T];
    int t = threadIdx.x;
    const int per = (NN + T - 1) / T;   // 49
    int beg = t * per;
    int end = beg + per; if (end > NN) end = NN;
    int s = 0;
    for (int i = beg; i < end; i++) s += g_cnt[i];
    ssum[t] = s;
    __syncthreads();
    for (int off = 1; off < T; off <<= 1) {
        int v = 0;
        if (t >= off) v = ssum[t - off];
        __syncthreads();
        ssum[t] += v;
        __syncthreads();
    }
    int run = (t == 0) ? 0 : ssum[t - 1];
    for (int i = beg; i < end; i++) {
        int c = g_cnt[i];
        g_rowptr[i] = run;
        g_cur[i]    = run;
        float d = (float)c;
        if (d < 0.5f) d += 1.0f;
        g_dinv[i] = rsqrtf(d);
        run += c;
    }
    if (t == T - 1) g_rowptr[NN] = ssum[T - 1];
}

// ---------------- scatter edges into CSR ------------------------------------
__global__ void __launch_bounds__(256) scatter_kernel(const int* __restrict__ row,
                                                      const int* __restrict__ col,
                                                      const float* __restrict__ attr) {
    int e = blockIdx.x * blockDim.x + threadIdx.x;
    if (e >= NE) return;
    int r = row[e], c = col[e];
    float v = g_dinv[r] * attr[e] * g_dinv[c];
    int pos = atomicAdd(&g_cur[r], 1);
    g_edge[pos] = make_int2(c, __float_as_int(v));
}

// ---------------- SpMM core: 16 lanes/node, broadcast edge + coalesced gather
// All 16 lanes of a group read the SAME g_edge[j] (HW broadcast, 1 sector),
// then gather x4[col*16+lane] -> one coalesced 256B region per edge.
// 4-edge unroll, two accumulators -> 4 independent gathers in flight/lane.
__device__ __forceinline__ float4 spmm_row(const float4* __restrict__ x4,
                                           int node, int lane) {
    int j   = g_rowptr[node];
    int end = g_rowptr[node + 1];
    float4 acc0 = make_float4(0.f, 0.f, 0.f, 0.f);
    float4 acc1 = make_float4(0.f, 0.f, 0.f, 0.f);

    for (; j + 4 <= end; j += 4) {
        int2 e0 = g_edge[j];
        int2 e1 = g_edge[j + 1];
        int2 e2 = g_edge[j + 2];
        int2 e3 = g_edge[j + 3];
        float v0 = __int_as_float(e0.y);
        float v1 = __int_as_float(e1.y);
        float v2 = __int_as_float(e2.y);
        float v3 = __int_as_float(e3.y);
        float4 a0 = __ldg(x4 + e0.x * 16 + lane);
        float4 a1 = __ldg(x4 + e1.x * 16 + lane);
        float4 a2 = __ldg(x4 + e2.x * 16 + lane);
        float4 a3 = __ldg(x4 + e3.x * 16 + lane);
        acc0.x = fmaf(v0, a0.x, acc0.x); acc0.y = fmaf(v0, a0.y, acc0.y);
        acc0.z = fmaf(v0, a0.z, acc0.z); acc0.w = fmaf(v0, a0.w, acc0.w);
        acc1.x = fmaf(v1, a1.x, acc1.x); acc1.y = fmaf(v1, a1.y, acc1.y);
        acc1.z = fmaf(v1, a1.z, acc1.z); acc1.w = fmaf(v1, a1.w, acc1.w);
        acc0.x = fmaf(v2, a2.x, acc0.x); acc0.y = fmaf(v2, a2.y, acc0.y);
        acc0.z = fmaf(v2, a2.z, acc0.z); acc0.w = fmaf(v2, a2.w, acc0.w);
        acc1.x = fmaf(v3, a3.x, acc1.x); acc1.y = fmaf(v3, a3.y, acc1.y);
        acc1.z = fmaf(v3, a3.z, acc1.z); acc1.w = fmaf(v3, a3.w, acc1.w);
    }
    for (; j < end; j++) {
        int2 e0 = g_edge[j];
        float v0 = __int_as_float(e0.y);
        float4 a0 = __ldg(x4 + e0.x * 16 + lane);
        acc0.x = fmaf(v0, a0.x, acc0.x); acc0.y = fmaf(v0, a0.y, acc0.y);
        acc0.z = fmaf(v0, a0.z, acc0.z); acc0.w = fmaf(v0, a0.w, acc0.w);
    }
    acc0.x += acc1.x; acc0.y += acc1.y; acc0.z += acc1.z; acc0.w += acc1.w;
    return acc0;
}

__global__ void __launch_bounds__(256) spmm_kernel(const float4* __restrict__ x4,
                                                   float4* __restrict__ y4) {
    int gt = blockIdx.x * blockDim.x + threadIdx.x;
    int node = gt >> 4;
    if (node >= NN) return;
    int lane = gt & 15;
    float4 acc = spmm_row(x4, node, lane);
    y4[node * 16 + lane] = acc;
}

// ---------------- final hop fused with output combination -------------------
// v3 = S*y2; out[n][L][d] = sum_k C[L][k] * (S^k x)[n][d]
__global__ void __launch_bounds__(256) spmm_out_kernel(const float4* __restrict__ y2src,
                                                       const float4* __restrict__ x0,
                                                       const float4* __restrict__ y1,
                                                       float4* __restrict__ out) {
    int gt = blockIdx.x * blockDim.x + threadIdx.x;
    int node = gt >> 4;
    if (node >= NN) return;
    int lane = gt & 15;
    float4 v3 = spmm_row(y2src, node, lane);

    int idx = node * 16 + lane;
    float4 v0 = x0[idx];
    float4 v1 = y1[idx];
    float4 v2 = y2src[idx];

    float4* op = out + node * 64 + lane;   // 256 floats/node = 64 float4
#pragma unroll
    for (int L = 0; L < 4; L++) {
        float c0 = g_C[L][0], c1 = g_C[L][1], c2 = g_C[L][2], c3 = g_C[L][3];
        float4 r;
        r.x = c0 * v0.x + c1 * v1.x + c2 * v2.x + c3 * v3.x;
        r.y = c0 * v0.y + c1 * v1.y + c2 * v2.y + c3 * v3.y;
        r.z = c0 * v0.z + c1 * v1.z + c2 * v2.z + c3 * v3.z;
        r.w = c0 * v0.w + c1 * v1.w + c2 * v2.w + c3 * v3.w;
        op[L * 16] = r;
    }
}

// ---------------- launcher ---------------------------------------------------
extern "C" void kernel_launch(void* const* d_in, const int* in_sizes, int n_in,
                              void* d_out, int out_size) {
    const float* x      = (const float*)d_in[0];
    const int*   ei     = (const int*)d_in[1];
    const int*   row    = ei;
    const int*   col    = ei + NE;
    const float* attr   = (const float*)d_in[2];
    const float* alphas = (const float*)d_in[3];
    const float* w      = (const float*)d_in[4];
    const float* a_arr  = (const float*)d_in[5];
    const float* b_arr  = (const float*)d_in[6];
    float*       out    = (float*)d_out;

    init_kernel<<<(NN + 255) / 256, 256>>>(alphas, w, a_arr, b_arr);
    hist_kernel<<<(NE + 255) / 256, 256>>>(row);
    scan_kernel<<<1, 1024>>>();
    scatter_kernel<<<(NE + 255) / 256, 256>>>(row, col, attr);

    const int spmm_threads = NN * 16;
    const int spmm_blocks = (spmm_threads + 255) / 256;
    spmm_kernel<<<spmm_blocks, 256>>>((const float4*)x, (float4*)g_y1);       // y1 = S x
    spmm_kernel<<<spmm_blocks, 256>>>((const float4*)g_y1, (float4*)g_y2);    // y2 = S y1
    spmm_out_kernel<<<spmm_blocks, 256>>>((const float4*)g_y2, (const float4*)x,
                                          (const float4*)g_y1, (float4*)out); // y3 + combine
}

// round 10
// speedup vs baseline: 14.1388x; 14.1388x over previous
#include <cuda_runtime.h>
#include <math.h>

#define NN 50000
#define NE 800000
#define DF 64
#define MM 11
#define NDEPTH 3

// ---------------- scratch (device globals — no allocation allowed) ----------
// NOTE: never pass these symbols' addresses from host code — on GB300 the
// host shadow address is ATS-reachable pageable memory (silent 14x slowdown).
// All selection happens inside device code.
__device__ int   g_cnt[NN];
__device__ int   g_cur[NN];          // running CSR fill cursor (init = rowptr)
__device__ int   g_rowptr[NN + 1];
__device__ float g_dinv[NN];
__device__ int2  g_edge[NE];         // (col, val-bits) per CSR slot
__device__ float g_y1[NN * DF];
__device__ float g_y2[NN * DF];
__device__ float g_C[4][4];          // out[L] = sum_k C[L][k] * S^k x

// ---------------- init: zero cnt + compute coefficients ---------------------
// Jacobi recursion with l=-1, r=1: (l+r)/(r-l)=0, 2/(r-l)=1.
__global__ void init_kernel(const float* __restrict__ alphas,
                            const float* __restrict__ w,
                            const float* __restrict__ a_arr,
                            const float* __restrict__ b_arr) {
    int i = blockIdx.x * blockDim.x + threadIdx.x;
    if (i < NN) g_cnt[i] = 0;

    if (blockIdx.x == 0) {
        __shared__ double sC[MM][4][4];
        int m = threadIdx.x;
        if (m < MM) {
            double a = (double)a_arr[m];
            double b = (double)b_arr[m];
            double wm = (double)w[m];
            double al[NDEPTH];
            for (int d = 0; d < NDEPTH; d++) al[d] = (double)alphas[d * MM + m];

            double Pm2[4] = {1.0, 0.0, 0.0, 0.0};              // P0
            double coef1 = (a - b) * 0.5;
            double coef2 = (a + b + 2.0) * 0.5;
            double Pm1[4] = {al[0] * coef1, al[0] * coef2, 0.0, 0.0};  // P1

            for (int k = 0; k < 4; k++) { sC[m][0][k] = wm * Pm2[k]; sC[m][1][k] = wm * Pm1[k]; }

            for (int Lk = 2; Lk <= NDEPTH; Lk++) {
                double Lf = (double)Lk;
                double coef_l     = 2.0 * Lf * (Lf + a + b) * (2.0 * Lf - 2.0 + a + b);
                double coef_lm1_1 = (2.0 * Lf + a + b - 1.0) * (2.0 * Lf + a + b) * (2.0 * Lf + a + b - 2.0);
                double coef_lm1_2 = (2.0 * Lf + a + b - 1.0) * (a * a - b * b);
                double coef_lm2   = 2.0 * (Lf - 1.0 + a) * (Lf - 1.0 + b) * (2.0 * Lf + a + b);
                double alL   = al[Lk - 1];
                double alLm1 = al[Lk - 2];
                double tmp1 = alL * (coef_lm1_1 / coef_l);
                double tmp2 = alL * (coef_lm1_2 / coef_l);
                double tmp3 = alL * alLm1 * (coef_lm2 / coef_l);
                double PL[4];
                PL[0] = -tmp2 * Pm1[0] - tmp3 * Pm2[0];
                for (int k = 1; k < 4; k++)
                    PL[k] = tmp1 * Pm1[k - 1] - tmp2 * Pm1[k] - tmp3 * Pm2[k];
                for (int k = 0; k < 4; k++) sC[m][Lk][k] = wm * PL[k];
                for (int k = 0; k < 4; k++) { Pm2[k] = Pm1[k]; Pm1[k] = PL[k]; }
            }
        }
        __syncthreads();
        int t = threadIdx.x;
        if (t < 16) {
            int L = t >> 2, k = t & 3;
            double s = 0.0;
            for (int mm = 0; mm < MM; mm++) s += sC[mm][L][k];
            g_C[L][k] = (float)s;
        }
    }
}

// ---------------- degree histogram ------------------------------------------
__global__ void __launch_bounds__(256) hist_kernel(const int* __restrict__ row) {
    int e = blockIdx.x * blockDim.x + threadIdx.x;
    if (e < NE) atomicAdd(&g_cnt[row[e]], 1);
}

// ---------------- scan (+ dinv + cursor init), single block -----------------
__global__ void __launch_bounds__(1024) scan_kernel() {
    const int T = 1024;
    __shared__ int ssum[T];
    int t = threadIdx.x;
    const int per = (NN + T - 1) / T;   // 49
    int beg = t * per;
    int end = beg + per; if (end > NN) end = NN;
    int s = 0;
    for (int i = beg; i < end; i++) s += g_cnt[i];
    ssum[t] = s;
    __syncthreads();
    for (int off = 1; off < T; off <<= 1) {
        int v = 0;
        if (t >= off) v = ssum[t - off];
        __syncthreads();
        ssum[t] += v;
        __syncthreads();
    }
    int run = (t == 0) ? 0 : ssum[t - 1];
    for (int i = beg; i < end; i++) {
        int c = g_cnt[i];
        g_rowptr[i] = run;
        g_cur[i]    = run;
        float d = (float)c;
        if (d < 0.5f) d += 1.0f;
        g_dinv[i] = rsqrtf(d);
        run += c;
    }
    if (t == T - 1) g_rowptr[NN] = ssum[T - 1];
}

// ---------------- scatter edges into CSR ------------------------------------
__global__ void __launch_bounds__(256) scatter_kernel(const int* __restrict__ row,
                                                      const int* __restrict__ col,
                                                      const float* __restrict__ attr) {
    int e = blockIdx.x * blockDim.x + threadIdx.x;
    if (e >= NE) return;
    int r = row[e], c = col[e];
    float v = g_dinv[r] * attr[e] * g_dinv[c];
    int pos = atomicAdd(&g_cur[r], 1);
    g_edge[pos] = make_int2(c, __float_as_int(v));
}

// ---------------- SpMM core: 16 lanes/node, broadcast edge + coalesced gather
// All 16 lanes of a group read the SAME g_edge[j] (HW broadcast, 1 sector),
// then gather x4[col*16+lane] -> one coalesced 256B region per edge.
// 4-edge unroll, two accumulators -> 4 independent gathers in flight/lane.
__device__ __forceinline__ float4 spmm_row(const float4* __restrict__ x4,
                                           int node, int lane) {
    int j   = g_rowptr[node];
    int end = g_rowptr[node + 1];
    float4 acc0 = make_float4(0.f, 0.f, 0.f, 0.f);
    float4 acc1 = make_float4(0.f, 0.f, 0.f, 0.f);

    for (; j + 4 <= end; j += 4) {
        int2 e0 = g_edge[j];
        int2 e1 = g_edge[j + 1];
        int2 e2 = g_edge[j + 2];
        int2 e3 = g_edge[j + 3];
        float v0 = __int_as_float(e0.y);
        float v1 = __int_as_float(e1.y);
        float v2 = __int_as_float(e2.y);
        float v3 = __int_as_float(e3.y);
        float4 a0 = __ldg(x4 + e0.x * 16 + lane);
        float4 a1 = __ldg(x4 + e1.x * 16 + lane);
        float4 a2 = __ldg(x4 + e2.x * 16 + lane);
        float4 a3 = __ldg(x4 + e3.x * 16 + lane);
        acc0.x = fmaf(v0, a0.x, acc0.x); acc0.y = fmaf(v0, a0.y, acc0.y);
        acc0.z = fmaf(v0, a0.z, acc0.z); acc0.w = fmaf(v0, a0.w, acc0.w);
        acc1.x = fmaf(v1, a1.x, acc1.x); acc1.y = fmaf(v1, a1.y, acc1.y);
        acc1.z = fmaf(v1, a1.z, acc1.z); acc1.w = fmaf(v1, a1.w, acc1.w);
        acc0.x = fmaf(v2, a2.x, acc0.x); acc0.y = fmaf(v2, a2.y, acc0.y);
        acc0.z = fmaf(v2, a2.z, acc0.z); acc0.w = fmaf(v2, a2.w, acc0.w);
        acc1.x = fmaf(v3, a3.x, acc1.x); acc1.y = fmaf(v3, a3.y, acc1.y);
        acc1.z = fmaf(v3, a3.z, acc1.z); acc1.w = fmaf(v3, a3.w, acc1.w);
    }
    for (; j < end; j++) {
        int2 e0 = g_edge[j];
        float v0 = __int_as_float(e0.y);
        float4 a0 = __ldg(x4 + e0.x * 16 + lane);
        acc0.x = fmaf(v0, a0.x, acc0.x); acc0.y = fmaf(v0, a0.y, acc0.y);
        acc0.z = fmaf(v0, a0.z, acc0.z); acc0.w = fmaf(v0, a0.w, acc0.w);
    }
    acc0.x += acc1.x; acc0.y += acc1.y; acc0.z += acc1.z; acc0.w += acc1.w;
    return acc0;
}

// mode 0: y1 = S x(ext);  mode 1: y2 = S y1   (pointers resolved DEVICE-side)
__global__ void __launch_bounds__(256) spmm_kernel(const float4* __restrict__ xext,
                                                   int mode) {
    int gt = blockIdx.x * blockDim.x + threadIdx.x;
    int node = gt >> 4;
    if (node >= NN) return;
    int lane = gt & 15;
    const float4* x4 = (mode == 0) ? xext : (const float4*)g_y1;
    float4*       y4 = (mode == 0) ? (float4*)g_y1 : (float4*)g_y2;
    float4 acc = spmm_row(x4, node, lane);
    y4[node * 16 + lane] = acc;
}

// ---------------- final hop fused with output combination -------------------
// v3 = S*y2; out[n][L][d] = sum_k C[L][k] * (S^k x)[n][d]
__global__ void __launch_bounds__(256) spmm_out_kernel(const float4* __restrict__ x0,
                                                       float4* __restrict__ out) {
    int gt = blockIdx.x * blockDim.x + threadIdx.x;
    int node = gt >> 4;
    if (node >= NN) return;
    int lane = gt & 15;
    const float4* y1 = (const float4*)g_y1;
    const float4* y2 = (const float4*)g_y2;
    float4 v3 = spmm_row(y2, node, lane);

    int idx = node * 16 + lane;
    float4 v0 = x0[idx];
    float4 v1 = y1[idx];
    float4 v2 = y2[idx];

    float4* op = out + node * 64 + lane;   // 256 floats/node = 64 float4
#pragma unroll
    for (int L = 0; L < 4; L++) {
        float c0 = g_C[L][0], c1 = g_C[L][1], c2 = g_C[L][2], c3 = g_C[L][3];
        float4 r;
        r.x = c0 * v0.x + c1 * v1.x + c2 * v2.x + c3 * v3.x;
        r.y = c0 * v0.y + c1 * v1.y + c2 * v2.y + c3 * v3.y;
        r.z = c0 * v0.z + c1 * v1.z + c2 * v2.z + c3 * v3.z;
        r.w = c0 * v0.w + c1 * v1.w + c2 * v2.w + c3 * v3.w;
        op[L * 16] = r;
    }
}

// ---------------- launcher ---------------------------------------------------
extern "C" void kernel_launch(void* const* d_in, const int* in_sizes, int n_in,
                              void* d_out, int out_size) {
    const float* x      = (const float*)d_in[0];
    const int*   ei     = (const int*)d_in[1];
    const int*   row    = ei;
    const int*   col    = ei + NE;
    const float* attr   = (const float*)d_in[2];
    const float* alphas = (const float*)d_in[3];
    const float* w      = (const float*)d_in[4];
    const float* a_arr  = (const float*)d_in[5];
    const float* b_arr  = (const float*)d_in[6];
    float*       out    = (float*)d_out;

    init_kernel<<<(NN + 255) / 256, 256>>>(alphas, w, a_arr, b_arr);
    hist_kernel<<<(NE + 255) / 256, 256>>>(row);
    scan_kernel<<<1, 1024>>>();
    scatter_kernel<<<(NE + 255) / 256, 256>>>(row, col, attr);

    const int spmm_threads = NN * 16;
    const int spmm_blocks = (spmm_threads + 255) / 256;
    spmm_kernel<<<spmm_blocks, 256>>>((const float4*)x, 0);   // y1 = S x
    spmm_kernel<<<spmm_blocks, 256>>>((const float4*)x, 1);   // y2 = S y1
    spmm_out_kernel<<<spmm_blocks, 256>>>((const float4*)x, (float4*)out); // y3 + combine
}